// round 16
// baseline (speedup 1.0000x reference)
#include <cuda_runtime.h>
#include <cuda_fp16.h>
#include <math.h>
#include <stdint.h>

// Problem constants
#define BATCH   128
#define TSEQ    256
#define CDIM    384
#define C4DIM   1536
#define NHEAD   6
#define HSZ     64
#define MTOK    (BATCH*TSEQ)      // 32768
#define QKVN    (3*CDIM)          // 1152

// ---------------- scratch (device globals; no allocations) ----------------
__device__ __half g_h[(size_t)MTOK*CDIM];        // ln1 output (fp16)
__device__ __half g_qkv[(size_t)MTOK*QKVN];      // fused qkv (fp16; Q pre-scaled by 1/8)
__device__ __half g_att[(size_t)MTOK*CDIM];      // attention output (fp16)
__device__ float  g_x2[(size_t)MTOK*CDIM];       // x + attn residual (fp32)
__device__ __half g_h2[(size_t)MTOK*CDIM];       // ln2 output (fp16)
__device__ __half g_hidden[(size_t)MTOK*C4DIM];  // FFN hidden post-GELU (fp16)
__device__ __half g_Wqkv[(size_t)QKVN*CDIM];     // [n][k] fp16
__device__ float  g_bqkv[QKVN];
__device__ __half g_Wo[(size_t)CDIM*CDIM];       // [n][k] fp16
__device__ __half g_W1[(size_t)C4DIM*CDIM];      // [n][k]
__device__ __half g_W2[(size_t)CDIM*C4DIM];      // [n][k]

// ---------------- PTX helpers ----------------
__device__ __forceinline__ uint32_t smem_u32(const void* p) {
    uint32_t a;
    asm("{ .reg .u64 t; cvta.to.shared.u64 t, %1; cvt.u32.u64 %0, t; }" : "=r"(a) : "l"(p));
    return a;
}
__device__ __forceinline__ void cp16s(uint32_t s, const void* g) {
    asm volatile("cp.async.ca.shared.global [%0], [%1], 16;\n" :: "r"(s), "l"(g));
}
__device__ __forceinline__ void cp_commit() { asm volatile("cp.async.commit_group;\n"); }
template<int NG> __device__ __forceinline__ void cp_wait() {
    asm volatile("cp.async.wait_group %0;\n" :: "n"(NG));
}
// fp16 mma, fp32 accumulate
__device__ __forceinline__ void mma_f16(float* c, const uint32_t* a, const uint32_t* b) {
    asm volatile(
        "mma.sync.aligned.m16n8k16.row.col.f32.f16.f16.f32 "
        "{%0,%1,%2,%3}, {%4,%5,%6,%7}, {%8,%9}, {%0,%1,%2,%3};\n"
        : "+f"(c[0]), "+f"(c[1]), "+f"(c[2]), "+f"(c[3])
        : "r"(a[0]), "r"(a[1]), "r"(a[2]), "r"(a[3]), "r"(b[0]), "r"(b[1]));
}
__device__ __forceinline__ void ldsm_x4(uint32_t* d, uint32_t addr) {
    asm volatile("ldmatrix.sync.aligned.m8n8.x4.shared.b16 {%0,%1,%2,%3}, [%4];"
                 : "=r"(d[0]), "=r"(d[1]), "=r"(d[2]), "=r"(d[3]) : "r"(addr));
}
__device__ __forceinline__ uint32_t h2u(float a, float b) {
    __half2 h = __floats2half2_rn(a, b);
    return *(uint32_t*)&h;
}

// ---------------- weight prep: transpose to [n][k] + fp16 ----------------
__global__ void wprep_kernel(const float* __restrict__ Wo, const float* __restrict__ W1,
                             const float* __restrict__ W2) {
    int idx = blockIdx.x * blockDim.x + threadIdx.x;
    const int n_o = CDIM * CDIM;
    const int n_1 = C4DIM * CDIM;
    const int n_2 = CDIM * C4DIM;
    if (idx < n_o) {
        int n = idx / CDIM, k = idx % CDIM;
        g_Wo[idx] = __float2half_rn(Wo[(size_t)k * CDIM + n]);
    } else if (idx < n_o + n_1) {
        int i = idx - n_o;
        int n = i / CDIM, k = i % CDIM;
        g_W1[i] = __float2half_rn(W1[(size_t)k * C4DIM + n]);
    } else if (idx < n_o + n_1 + n_2) {
        int i = idx - n_o - n_1;
        int n = i / C4DIM, k = i % C4DIM;
        g_W2[i] = __float2half_rn(W2[(size_t)k * CDIM + n]);
    }
}

// ---------------- repack per-head Q/K/V weights -> [n][k] fp16 ----------------
__global__ void repack_kernel(const float* __restrict__ Wq, const float* __restrict__ Wk,
                              const float* __restrict__ Wv, const float* __restrict__ bq,
                              const float* __restrict__ bk, const float* __restrict__ bv) {
    int idx = blockIdx.x * blockDim.x + threadIdx.x;
    int total = QKVN * CDIM;
    if (idx >= total) return;
    int n = idx / CDIM;
    int k = idx % CDIM;
    int j = n / CDIM;
    int hd = n % CDIM;
    int h = hd >> 6, d = hd & 63;
    const float* W = (j == 0) ? Wq : ((j == 1) ? Wk : Wv);
    g_Wqkv[idx] = __float2half_rn(W[((size_t)h * CDIM + k) * HSZ + d]);
    if (k == 0) {
        const float* bb = (j == 0) ? bq : ((j == 1) ? bk : bv);
        g_bqkv[n] = bb[hd];
    }
}

// ---------------- LayerNorm (fp16 output; consumed only by GEMMs) ----------------
__global__ void ln_kernel(const float* __restrict__ x, const float* __restrict__ g,
                          const float* __restrict__ b, __half* __restrict__ out) {
    int row = blockIdx.x;
    int tid = threadIdx.x;
    const float* xr = x + (size_t)row * CDIM;
    float v0 = xr[tid], v1 = xr[tid + 128], v2 = xr[tid + 256];
    float s = v0 + v1 + v2;
    float sq = v0 * v0 + v1 * v1 + v2 * v2;
    #pragma unroll
    for (int o = 16; o > 0; o >>= 1) {
        s  += __shfl_down_sync(0xffffffffu, s, o);
        sq += __shfl_down_sync(0xffffffffu, sq, o);
    }
    __shared__ float sh[8];
    int w = tid >> 5;
    if ((tid & 31) == 0) { sh[w] = s; sh[4 + w] = sq; }
    __syncthreads();
    if (tid == 0) {
        float ts = sh[0] + sh[1] + sh[2] + sh[3];
        float tq = sh[4] + sh[5] + sh[6] + sh[7];
        float mu = ts * (1.0f / CDIM);
        float var = tq * (1.0f / CDIM) - mu * mu;
        sh[0] = mu;
        sh[4] = rsqrtf(var + 1e-5f);
    }
    __syncthreads();
    float mu = sh[0], rs = sh[4];
    __half* orow = out + (size_t)row * CDIM;
    orow[tid]       = __float2half_rn((v0 - mu) * rs * g[tid]       + b[tid]);
    orow[tid + 128] = __float2half_rn((v1 - mu) * rs * g[tid + 128] + b[tid + 128]);
    orow[tid + 256] = __float2half_rn((v2 - mu) * rs * g[tid + 256] + b[tid + 256]);
}

// ---------------- fp16 tensor-core GEMM (ldmatrix, BK=64, 3-stage) ----------------
// A: [M][K] half. Bt: [N][K] half (k-major). C: fp32 or fp16 per half_out.
// 128x128 CTA tile, BK=64, 256 threads = 8 warps (2 in M x 4 in N), warp tile 64x32.
// 3-stage cp.async ring: cp_wait<1> keeps one load in flight; slot (t+2)%3 is the
// one computed at t-1 (finished before this iteration's barrier) -> race-free.
#define NSTAGE 3
#define HPAD   72                       // halves per smem row (144B) - conflict-free
#define TILE_H (128*HPAD)
#define STAGE_H (2*TILE_H)
#define HG_SMEM (NSTAGE*STAGE_H*2)      // 110592 B

__global__ __launch_bounds__(256, 2) void hgemm(
    const __half* __restrict__ A, const __half* __restrict__ Bt,
    const float* __restrict__ bias, const float* __restrict__ res,
    void* __restrict__ Cout, int M, int N, int K, int gelu_act, int half_out, int scale_q)
{
    extern __shared__ __half hsm[];
    uint32_t sb = smem_u32(hsm);
    int tid  = threadIdx.x;
    int bm   = blockIdx.y * 128;
    int bn   = blockIdx.x * 128;
    int warp = tid >> 5, lane = tid & 31;
    int wm   = (warp & 1) * 64;
    int wn   = (warp >> 1) * 32;
    int quad = lane >> 2, r = lane & 3;

    // ldmatrix per-lane address terms (bytes)
    uint32_t lane_a = (uint32_t)((lane & 15) * HPAD + ((lane >> 4) << 3)) * 2;
    uint32_t lane_b = (uint32_t)((((lane >> 4) << 3) + (lane & 7)) * HPAD + (lane & 8)) * 2;

    float acc[4][4][4];
    #pragma unroll
    for (int i = 0; i < 4; i++)
        #pragma unroll
        for (int j = 0; j < 4; j++)
            #pragma unroll
            for (int q = 0; q < 4; q++) acc[i][j][q] = 0.f;

    int nt = K / 64;

    auto load_stage = [&](int slot, int k0) {
        uint32_t abase = sb + slot * (STAGE_H * 2);
        uint32_t bbase = abase + TILE_H * 2;
        #pragma unroll
        for (int l = 0; l < 4; l++) {
            int idx = tid + l * 256;
            int row = idx >> 3, u = idx & 7;
            cp16s(abase + row * (HPAD * 2) + u * 16, A + (size_t)(bm + row) * K + k0 + u * 8);
        }
        #pragma unroll
        for (int l = 0; l < 4; l++) {
            int idx = tid + l * 256;
            int row = idx >> 3, u = idx & 7;
            cp16s(bbase + row * (HPAD * 2) + u * 16, Bt + (size_t)(bn + row) * K + k0 + u * 8);
        }
        cp_commit();
    };

    load_stage(0, 0);
    load_stage(1, 64);

    for (int t = 0; t < nt; t++) {
        if (t + 2 < nt) cp_wait<1>(); else cp_wait<0>();
        __syncthreads();
        if (t + 2 < nt) load_stage((t + 2) % NSTAGE, (t + 2) * 64);

        uint32_t sa    = sb + (t % NSTAGE) * (STAGE_H * 2);
        uint32_t abase = sa + wm * (HPAD * 2) + lane_a;
        uint32_t bbase = sa + TILE_H * 2 + wn * (HPAD * 2) + lane_b;

        #pragma unroll
        for (int ks = 0; ks < 4; ks++) {
            uint32_t af[4][4], b01[4], b23[4];
            #pragma unroll
            for (int mf = 0; mf < 4; mf++)
                ldsm_x4(af[mf], abase + mf * (16 * HPAD * 2) + ks * 32);
            ldsm_x4(b01, bbase + ks * 32);
            ldsm_x4(b23, bbase + 16 * (HPAD * 2) + ks * 32);
            uint32_t bf[4][2] = {{b01[0], b01[1]}, {b01[2], b01[3]},
                                 {b23[0], b23[1]}, {b23[2], b23[3]}};
            #pragma unroll
            for (int mf = 0; mf < 4; mf++)
                #pragma unroll
                for (int nf = 0; nf < 4; nf++)
                    mma_f16(acc[mf][nf], af[mf], bf[nf]);
        }
    }

    // epilogue: bias (+gelu) (+res) (+Q prescale), fp32 math; fp32 or fp16 store
    #pragma unroll
    for (int mf = 0; mf < 4; mf++) {
        #pragma unroll
        for (int nf = 0; nf < 4; nf++) {
            int col = bn + wn + nf * 8 + 2 * r;
            float bia0 = bias[col], bia1 = bias[col + 1];
            float qs = (scale_q && col < CDIM) ? 0.125f : 1.0f;
            #pragma unroll
            for (int hh = 0; hh < 2; hh++) {
                int row = bm + wm + mf * 16 + quad + hh * 8;
                float v0 = (acc[mf][nf][hh * 2 + 0] + bia0) * qs;
                float v1 = (acc[mf][nf][hh * 2 + 1] + bia1) * qs;
                if (gelu_act) {
                    v0 = 0.5f * v0 * (1.0f + erff(v0 * 0.70710678118f));
                    v1 = 0.5f * v1 * (1.0f + erff(v1 * 0.70710678118f));
                }
                if (res) {
                    const float2 rr = *(const float2*)&res[(size_t)row * N + col];
                    v0 += rr.x; v1 += rr.y;
                }
                if (half_out) {
                    __half2* cp = (__half2*)((__half*)Cout + (size_t)row * N + col);
                    *cp = __floats2half2_rn(v0, v1);
                } else {
                    float* cp = (float*)Cout + (size_t)row * N + col;
                    *(float2*)cp = make_float2(v0, v1);
                }
            }
        }
    }
}

// ---------------- fp16 flash attention, register P, 2 CTAs per (b,h) ----------------
// Grid = B*H*2. Each CTA: 128 query rows (8 warps x 16), full 256-key K/V staged.
// Q pre-scaled by 1/8. S C-fragments exp'd and packed directly into PV A-fragments.
// ~96 regs/thread + 70.7KB smem -> 2 CTAs/SM (16 warps).
#define KSTR 72
#define VSTR 264
#define ATTN_SMEM ((256*KSTR + 64*VSTR) * 2)   // 70656 B

__global__ __launch_bounds__(256, 2) void attn_tc_kernel(const __half* __restrict__ qkv,
                                                         __half* __restrict__ att) {
    extern __shared__ __half asm_h[];
    __half* Kh = asm_h;                               // [256][KSTR]
    __half* Vt = asm_h + 256 * KSTR;                  // [64][VSTR] (transposed V)
    int tid = threadIdx.x, warp = tid >> 5, lane = tid & 31;
    int quad = lane >> 2, r = lane & 3;

    int blk = blockIdx.x;
    int bh = blk >> 1, qh = blk & 1;
    int b = bh / NHEAD, h = bh % NHEAD;
    const __half* base = qkv + (size_t)b * TSEQ * QKVN + h * HSZ;

    // ---- stage K (direct copy) and V (transposed); thread t = seq row t ----
    {
        const uint2* ks = (const uint2*)(base + (size_t)tid * QKVN + CDIM);
        const uint2* vs = (const uint2*)(base + (size_t)tid * QKVN + 2 * CDIM);
        uint2* kd = (uint2*)(Kh + tid * KSTR);
        #pragma unroll
        for (int i = 0; i < 16; i++) kd[i] = __ldg(&ks[i]);
        #pragma unroll
        for (int i = 0; i < 16; i++) {
            uint2 u = __ldg(&vs[i]);
            __half2 lo = *(__half2*)&u.x;
            __half2 hi = *(__half2*)&u.y;
            Vt[(4*i + 0) * VSTR + tid] = __low2half(lo);
            Vt[(4*i + 1) * VSTR + tid] = __high2half(lo);
            Vt[(4*i + 2) * VSTR + tid] = __low2half(hi);
            Vt[(4*i + 3) * VSTR + tid] = __high2half(hi);
        }
    }

    // ---- Q fragments: direct uint32 reads of packed half2 pairs ----
    int q0 = qh * 128 + warp * 16;
    uint32_t aq[4][4];
    {
        const __half* qr0 = base + (size_t)(q0 + quad) * QKVN;
        const __half* qr1 = qr0 + (size_t)8 * QKVN;
        #pragma unroll
        for (int kk = 0; kk < 4; kk++) {
            int kb = kk * 16;
            aq[kk][0] = __ldg((const uint32_t*)(qr0 + kb + 2*r));
            aq[kk][1] = __ldg((const uint32_t*)(qr1 + kb + 2*r));
            aq[kk][2] = __ldg((const uint32_t*)(qr0 + kb + 2*r + 8));
            aq[kk][3] = __ldg((const uint32_t*)(qr1 + kb + 2*r + 8));
        }
    }
    __syncthreads();

    float oacc[8][4];
    #pragma unroll
    for (int n = 0; n < 8; n++)
        #pragma unroll
        for (int q = 0; q < 4; q++) oacc[n][q] = 0.f;
    float rsum[2] = {0.f, 0.f};

    for (int s0 = 0; s0 < TSEQ; s0 += 64) {
        // ---- S = Q K^T for all 8 key n-tiles of this chunk ----
        float sacc[8][4];
        #pragma unroll
        for (int j = 0; j < 8; j++)
            #pragma unroll
            for (int q = 0; q < 4; q++) sacc[j][q] = 0.f;

        #pragma unroll
        for (int kk = 0; kk < 4; kk++) {
            #pragma unroll
            for (int j = 0; j < 8; j++) {
                const __half* kp = Kh + (size_t)(s0 + j * 8 + quad) * KSTR
                                   + kk * 16 + 2 * r;
                uint32_t bf[2] = { *(const uint32_t*)kp, *(const uint32_t*)(kp + 8) };
                mma_f16(sacc[j], aq[kk], bf);
            }
        }

        // ---- exp + pack directly into PV A-fragments (C-frag == A-frag map) ----
        uint32_t ap[4][4];
        #pragma unroll
        for (int j = 0; j < 8; j++) {
            float w0 = __expf(sacc[j][0]);
            float w1 = __expf(sacc[j][1]);
            float w2 = __expf(sacc[j][2]);
            float w3 = __expf(sacc[j][3]);
            rsum[0] += w0 + w1;
            rsum[1] += w2 + w3;
            int kk = j >> 1, hi = (j & 1) * 2;
            ap[kk][hi]     = h2u(w0, w1);
            ap[kk][hi + 1] = h2u(w2, w3);
        }

        // ---- O += P V  (B = Vt [n=d][k=seq]) ----
        #pragma unroll
        for (int kk = 0; kk < 4; kk++) {
            #pragma unroll
            for (int n = 0; n < 8; n++) {
                const __half* vp = Vt + (size_t)(n * 8 + quad) * VSTR + s0 + kk * 16 + 2 * r;
                uint32_t bf[2] = { *(const uint32_t*)vp, *(const uint32_t*)(vp + 8) };
                mma_f16(oacc[n], ap[kk], bf);
            }
        }
    }

    // ---- normalize + write (fp16) ----
    {
        float v0 = rsum[0], v1 = rsum[1];
        v0 += __shfl_xor_sync(0xffffffffu, v0, 1);
        v0 += __shfl_xor_sync(0xffffffffu, v0, 2);
        v1 += __shfl_xor_sync(0xffffffffu, v1, 1);
        v1 += __shfl_xor_sync(0xffffffffu, v1, 2);
        float inv0 = 1.0f / v0, inv1 = 1.0f / v1;
        int row0 = q0 + quad;
        __half* o0 = att + ((size_t)b * TSEQ + row0) * CDIM + h * HSZ;
        __half* o1 = o0 + (size_t)8 * CDIM;
        #pragma unroll
        for (int n = 0; n < 8; n++) {
            int col = n * 8 + 2 * r;
            *(__half2*)&o0[col] = __floats2half2_rn(oacc[n][0] * inv0,
                                                    oacc[n][1] * inv0);
            *(__half2*)&o1[col] = __floats2half2_rn(oacc[n][2] * inv1,
                                                    oacc[n][3] * inv1);
        }
    }
}

// ---------------- launch ----------------
extern "C" void kernel_launch(void* const* d_in, const int* in_sizes, int n_in,
                              void* d_out, int out_size) {
    const float* x   = (const float*)d_in[0];
    const float* Wq  = (const float*)d_in[1];
    const float* bq  = (const float*)d_in[2];
    const float* Wk  = (const float*)d_in[3];
    const float* bk  = (const float*)d_in[4];
    const float* Wv  = (const float*)d_in[5];
    const float* bv  = (const float*)d_in[6];
    const float* Wo  = (const float*)d_in[7];
    const float* bo  = (const float*)d_in[8];
    const float* W1  = (const float*)d_in[9];
    const float* b1  = (const float*)d_in[10];
    const float* W2  = (const float*)d_in[11];
    const float* b2  = (const float*)d_in[12];
    const float* g1  = (const float*)d_in[13];
    const float* be1 = (const float*)d_in[14];
    const float* g2  = (const float*)d_in[15];
    const float* be2 = (const float*)d_in[16];
    float* out = (float*)d_out;

    __half *p_h, *p_qkv, *p_att, *p_h2, *p_hidden, *p_Wqkv, *p_Wo, *p_W1, *p_W2;
    float *p_x2, *p_bqkv;
    cudaGetSymbolAddress((void**)&p_h,      g_h);
    cudaGetSymbolAddress((void**)&p_qkv,    g_qkv);
    cudaGetSymbolAddress((void**)&p_att,    g_att);
    cudaGetSymbolAddress((void**)&p_x2,     g_x2);
    cudaGetSymbolAddress((void**)&p_h2,     g_h2);
    cudaGetSymbolAddress((void**)&p_hidden, g_hidden);
    cudaGetSymbolAddress((void**)&p_Wqkv,   g_Wqkv);
    cudaGetSymbolAddress((void**)&p_bqkv,   g_bqkv);
    cudaGetSymbolAddress((void**)&p_Wo,     g_Wo);
    cudaGetSymbolAddress((void**)&p_W1,     g_W1);
    cudaGetSymbolAddress((void**)&p_W2,     g_W2);

    // Idempotent, non-stream, deterministic: safe on every call (no static guards).
    cudaFuncSetAttribute(attn_tc_kernel, cudaFuncAttributeMaxDynamicSharedMemorySize,
                         ATTN_SMEM);
    cudaFuncSetAttribute(hgemm, cudaFuncAttributeMaxDynamicSharedMemorySize,
                         HG_SMEM);

    // 0. weight prep (transpose + fp16)
    {
        int total = CDIM*CDIM + C4DIM*CDIM + CDIM*C4DIM;
        wprep_kernel<<<(total + 255) / 256, 256>>>(Wo, W1, W2);
    }
    {
        int total = QKVN * CDIM;
        repack_kernel<<<(total + 255) / 256, 256>>>(Wq, Wk, Wv, bq, bk, bv);
    }
    // 2. ln1 -> fp16
    ln_kernel<<<MTOK, 128>>>(x, g1, be1, p_h);
    // 3. fused QKV projection (fp16 TC) -> fp16 qkv, Q pre-scaled by 1/8
    hgemm<<<dim3(QKVN / 128, MTOK / 128), 256, HG_SMEM>>>(
        p_h, p_Wqkv, p_bqkv, nullptr, p_qkv, MTOK, QKVN, CDIM, 0, 1, 1);
    // 4. attention (fp16 TC flash, register P, 2 CTAs per head) -> fp16 att
    attn_tc_kernel<<<BATCH * NHEAD * 2, 256, ATTN_SMEM>>>(p_qkv, p_att);
    // 5. out projection + residual (fp16 TC) -> fp32 x2
    hgemm<<<dim3(CDIM / 128, MTOK / 128), 256, HG_SMEM>>>(
        p_att, p_Wo, bo, x, p_x2, MTOK, CDIM, CDIM, 0, 0, 0);
    // 6. ln2 -> fp16
    ln_kernel<<<MTOK, 128>>>(p_x2, g2, be2, p_h2);
    // 7. FFN up + GELU (fp16 TC) -> fp16 hidden
    hgemm<<<dim3(C4DIM / 128, MTOK / 128), 256, HG_SMEM>>>(
        p_h2, p_W1, b1, nullptr, p_hidden, MTOK, C4DIM, CDIM, 1, 1, 0);
    // 8. FFN down + bias + residual -> fp32 out
    hgemm<<<dim3(CDIM / 128, MTOK / 128), 256, HG_SMEM>>>(
        p_hidden, p_W2, b2, p_x2, out, MTOK, CDIM, C4DIM, 0, 0, 0);
}

// round 17
// speedup vs baseline: 1.2125x; 1.2125x over previous
#include <cuda_runtime.h>
#include <cuda_fp16.h>
#include <math.h>
#include <stdint.h>

// Problem constants
#define BATCH   128
#define TSEQ    256
#define CDIM    384
#define C4DIM   1536
#define NHEAD   6
#define HSZ     64
#define MTOK    (BATCH*TSEQ)      // 32768
#define QKVN    (3*CDIM)          // 1152

// ---------------- scratch (device globals; no allocations) ----------------
__device__ __half g_h[(size_t)MTOK*CDIM];        // ln1 output (fp16)
__device__ __half g_qkv[(size_t)MTOK*QKVN];      // fused qkv (fp16; Q pre-scaled by 1/8)
__device__ __half g_att[(size_t)MTOK*CDIM];      // attention output (fp16)
__device__ float  g_x2[(size_t)MTOK*CDIM];       // x + attn residual (fp32)
__device__ __half g_h2[(size_t)MTOK*CDIM];       // ln2 output (fp16)
__device__ __half g_hidden[(size_t)MTOK*C4DIM];  // FFN hidden post-GELU (fp16)
__device__ __half g_Wqkv[(size_t)QKVN*CDIM];     // [n][k] fp16
__device__ float  g_bqkv[QKVN];
__device__ __half g_Wo[(size_t)CDIM*CDIM];       // [n][k] fp16
__device__ __half g_W1[(size_t)C4DIM*CDIM];      // [n][k]
__device__ __half g_W2[(size_t)CDIM*C4DIM];      // [n][k]

// ---------------- PTX helpers ----------------
__device__ __forceinline__ uint32_t smem_u32(const void* p) {
    uint32_t a;
    asm("{ .reg .u64 t; cvta.to.shared.u64 t, %1; cvt.u32.u64 %0, t; }" : "=r"(a) : "l"(p));
    return a;
}
__device__ __forceinline__ void cp16s(uint32_t s, const void* g) {
    asm volatile("cp.async.ca.shared.global [%0], [%1], 16;\n" :: "r"(s), "l"(g));
}
__device__ __forceinline__ void cp_commit() { asm volatile("cp.async.commit_group;\n"); }
template<int NG> __device__ __forceinline__ void cp_wait() {
    asm volatile("cp.async.wait_group %0;\n" :: "n"(NG));
}
// fp16 mma, fp32 accumulate
__device__ __forceinline__ void mma_f16(float* c, const uint32_t* a, const uint32_t* b) {
    asm volatile(
        "mma.sync.aligned.m16n8k16.row.col.f32.f16.f16.f32 "
        "{%0,%1,%2,%3}, {%4,%5,%6,%7}, {%8,%9}, {%0,%1,%2,%3};\n"
        : "+f"(c[0]), "+f"(c[1]), "+f"(c[2]), "+f"(c[3])
        : "r"(a[0]), "r"(a[1]), "r"(a[2]), "r"(a[3]), "r"(b[0]), "r"(b[1]));
}
__device__ __forceinline__ void ldsm_x4(uint32_t* d, uint32_t addr) {
    asm volatile("ldmatrix.sync.aligned.m8n8.x4.shared.b16 {%0,%1,%2,%3}, [%4];"
                 : "=r"(d[0]), "=r"(d[1]), "=r"(d[2]), "=r"(d[3]) : "r"(addr));
}
__device__ __forceinline__ uint32_t h2u(float a, float b) {
    __half2 h = __floats2half2_rn(a, b);
    return *(uint32_t*)&h;
}

// ---------------- weight prep: transpose to [n][k] + fp16 ----------------
__global__ void wprep_kernel(const float* __restrict__ Wo, const float* __restrict__ W1,
                             const float* __restrict__ W2) {
    int idx = blockIdx.x * blockDim.x + threadIdx.x;
    const int n_o = CDIM * CDIM;
    const int n_1 = C4DIM * CDIM;
    const int n_2 = CDIM * C4DIM;
    if (idx < n_o) {
        int n = idx / CDIM, k = idx % CDIM;
        g_Wo[idx] = __float2half_rn(Wo[(size_t)k * CDIM + n]);
    } else if (idx < n_o + n_1) {
        int i = idx - n_o;
        int n = i / CDIM, k = i % CDIM;
        g_W1[i] = __float2half_rn(W1[(size_t)k * C4DIM + n]);
    } else if (idx < n_o + n_1 + n_2) {
        int i = idx - n_o - n_1;
        int n = i / C4DIM, k = i % C4DIM;
        g_W2[i] = __float2half_rn(W2[(size_t)k * CDIM + n]);
    }
}

// ---------------- repack per-head Q/K/V weights -> [n][k] fp16 ----------------
__global__ void repack_kernel(const float* __restrict__ Wq, const float* __restrict__ Wk,
                              const float* __restrict__ Wv, const float* __restrict__ bq,
                              const float* __restrict__ bk, const float* __restrict__ bv) {
    int idx = blockIdx.x * blockDim.x + threadIdx.x;
    int total = QKVN * CDIM;
    if (idx >= total) return;
    int n = idx / CDIM;
    int k = idx % CDIM;
    int j = n / CDIM;
    int hd = n % CDIM;
    int h = hd >> 6, d = hd & 63;
    const float* W = (j == 0) ? Wq : ((j == 1) ? Wk : Wv);
    g_Wqkv[idx] = __float2half_rn(W[((size_t)h * CDIM + k) * HSZ + d]);
    if (k == 0) {
        const float* bb = (j == 0) ? bq : ((j == 1) ? bk : bv);
        g_bqkv[n] = bb[hd];
    }
}

// ---------------- LayerNorm: one WARP per row (no smem, no barriers) ----------------
// 256 threads = 8 warps, 8 rows per block. Lane reads cols lane+32*i (i<12).
__global__ __launch_bounds__(256) void ln_kernel(
    const float* __restrict__ x, const float* __restrict__ g,
    const float* __restrict__ b, __half* __restrict__ out)
{
    int warp = threadIdx.x >> 5, lane = threadIdx.x & 31;
    int row = blockIdx.x * 8 + warp;
    const float* xr = x + (size_t)row * CDIM;

    float v[12];
    float s = 0.f, sq = 0.f;
    #pragma unroll
    for (int i = 0; i < 12; i++) {
        v[i] = xr[lane + 32 * i];
        s += v[i];
        sq += v[i] * v[i];
    }
    #pragma unroll
    for (int o = 16; o > 0; o >>= 1) {
        s  += __shfl_xor_sync(0xffffffffu, s, o);
        sq += __shfl_xor_sync(0xffffffffu, sq, o);
    }
    float mu = s * (1.0f / CDIM);
    float var = sq * (1.0f / CDIM) - mu * mu;
    float rs = rsqrtf(var + 1e-5f);

    __half* orow = out + (size_t)row * CDIM;
    #pragma unroll
    for (int i = 0; i < 12; i++) {
        int c = lane + 32 * i;
        orow[c] = __float2half_rn((v[i] - mu) * rs * g[c] + b[c]);
    }
}

// ---------------- fp16 tensor-core GEMM (ldmatrix, BK=64, 2-stage) ----------------
// A: [M][K] half. Bt: [N][K] half (k-major). C: fp32 or fp16 per half_out.
// 128x128 CTA tile, BK=64, 256 threads = 8 warps (2 in M x 4 in N), warp tile 64x32.
// One __syncthreads per 64-k tile; load issued AFTER the barrier (race-free slot reuse).
#define NSTAGE 2
#define HPAD   72                       // halves per smem row (144B) - conflict-free
#define TILE_H (128*HPAD)
#define STAGE_H (2*TILE_H)
#define HG_SMEM (NSTAGE*STAGE_H*2)      // 73728 B

__global__ __launch_bounds__(256, 2) void hgemm(
    const __half* __restrict__ A, const __half* __restrict__ Bt,
    const float* __restrict__ bias, const float* __restrict__ res,
    void* __restrict__ Cout, int M, int N, int K, int gelu_act, int half_out, int scale_q)
{
    extern __shared__ __half hsm[];
    uint32_t sb = smem_u32(hsm);
    int tid  = threadIdx.x;
    int bm   = blockIdx.y * 128;
    int bn   = blockIdx.x * 128;
    int warp = tid >> 5, lane = tid & 31;
    int wm   = (warp & 1) * 64;
    int wn   = (warp >> 1) * 32;
    int quad = lane >> 2, r = lane & 3;

    // ldmatrix per-lane address terms (bytes)
    uint32_t lane_a = (uint32_t)((lane & 15) * HPAD + ((lane >> 4) << 3)) * 2;
    uint32_t lane_b = (uint32_t)((((lane >> 4) << 3) + (lane & 7)) * HPAD + (lane & 8)) * 2;

    float acc[4][4][4];
    #pragma unroll
    for (int i = 0; i < 4; i++)
        #pragma unroll
        for (int j = 0; j < 4; j++)
            #pragma unroll
            for (int q = 0; q < 4; q++) acc[i][j][q] = 0.f;

    int nt = K / 64;

    auto load_stage = [&](int slot, int k0) {
        uint32_t abase = sb + slot * (STAGE_H * 2);
        uint32_t bbase = abase + TILE_H * 2;
        #pragma unroll
        for (int l = 0; l < 4; l++) {
            int idx = tid + l * 256;
            int row = idx >> 3, u = idx & 7;
            cp16s(abase + row * (HPAD * 2) + u * 16, A + (size_t)(bm + row) * K + k0 + u * 8);
        }
        #pragma unroll
        for (int l = 0; l < 4; l++) {
            int idx = tid + l * 256;
            int row = idx >> 3, u = idx & 7;
            cp16s(bbase + row * (HPAD * 2) + u * 16, Bt + (size_t)(bn + row) * K + k0 + u * 8);
        }
        cp_commit();
    };

    load_stage(0, 0);

    for (int t = 0; t < nt; t++) {
        cp_wait<0>();
        __syncthreads();
        if (t + 1 < nt) load_stage((t + 1) & 1, (t + 1) * 64);

        uint32_t sa    = sb + (t & 1) * (STAGE_H * 2);
        uint32_t abase = sa + wm * (HPAD * 2) + lane_a;
        uint32_t bbase = sa + TILE_H * 2 + wn * (HPAD * 2) + lane_b;

        #pragma unroll
        for (int ks = 0; ks < 4; ks++) {
            uint32_t af[4][4], b01[4], b23[4];
            #pragma unroll
            for (int mf = 0; mf < 4; mf++)
                ldsm_x4(af[mf], abase + mf * (16 * HPAD * 2) + ks * 32);
            ldsm_x4(b01, bbase + ks * 32);
            ldsm_x4(b23, bbase + 16 * (HPAD * 2) + ks * 32);
            uint32_t bf[4][2] = {{b01[0], b01[1]}, {b01[2], b01[3]},
                                 {b23[0], b23[1]}, {b23[2], b23[3]}};
            #pragma unroll
            for (int mf = 0; mf < 4; mf++)
                #pragma unroll
                for (int nf = 0; nf < 4; nf++)
                    mma_f16(acc[mf][nf], af[mf], bf[nf]);
        }
    }

    // epilogue: bias (+gelu) (+res) (+Q prescale), fp32 math; fp32 or fp16 store
    #pragma unroll
    for (int mf = 0; mf < 4; mf++) {
        #pragma unroll
        for (int nf = 0; nf < 4; nf++) {
            int col = bn + wn + nf * 8 + 2 * r;
            float bia0 = bias[col], bia1 = bias[col + 1];
            float qs = (scale_q && col < CDIM) ? 0.125f : 1.0f;
            #pragma unroll
            for (int hh = 0; hh < 2; hh++) {
                int row = bm + wm + mf * 16 + quad + hh * 8;
                float v0 = (acc[mf][nf][hh * 2 + 0] + bia0) * qs;
                float v1 = (acc[mf][nf][hh * 2 + 1] + bia1) * qs;
                if (gelu_act) {
                    v0 = 0.5f * v0 * (1.0f + erff(v0 * 0.70710678118f));
                    v1 = 0.5f * v1 * (1.0f + erff(v1 * 0.70710678118f));
                }
                if (res) {
                    const float2 rr = *(const float2*)&res[(size_t)row * N + col];
                    v0 += rr.x; v1 += rr.y;
                }
                if (half_out) {
                    __half2* cp = (__half2*)((__half*)Cout + (size_t)row * N + col);
                    *cp = __floats2half2_rn(v0, v1);
                } else {
                    float* cp = (float*)Cout + (size_t)row * N + col;
                    *(float2*)cp = make_float2(v0, v1);
                }
            }
        }
    }
}

// ---------------- fp16 flash attention, FA2-style register P ----------------
// One CTA per (b,h). 8 warps x 32 query rows. Q pre-scaled by 1/8.
// S C-fragments exp'd and repacked DIRECTLY into PV A-fragments (no P smem).
#define KSTR 72
#define VSTR 264
#define ATTN_SMEM ((256*KSTR + 64*VSTR) * 2)   // 70656 B

__global__ __launch_bounds__(256, 1) void attn_tc_kernel(const __half* __restrict__ qkv,
                                                         __half* __restrict__ att) {
    extern __shared__ __half asm_h[];
    __half* Kh = asm_h;                               // [256][KSTR]
    __half* Vt = asm_h + 256 * KSTR;                  // [64][VSTR] (transposed V)
    int tid = threadIdx.x, warp = tid >> 5, lane = tid & 31;
    int quad = lane >> 2, r = lane & 3;

    int bh = blockIdx.x;
    int b = bh / NHEAD, h = bh % NHEAD;
    const __half* base = qkv + (size_t)b * TSEQ * QKVN + h * HSZ;

    // ---- stage K (direct copy) and V (transposed); thread t = seq row t ----
    {
        const uint2* ks = (const uint2*)(base + (size_t)tid * QKVN + CDIM);
        const uint2* vs = (const uint2*)(base + (size_t)tid * QKVN + 2 * CDIM);
        uint2* kd = (uint2*)(Kh + tid * KSTR);
        #pragma unroll
        for (int i = 0; i < 16; i++) kd[i] = __ldg(&ks[i]);
        #pragma unroll
        for (int i = 0; i < 16; i++) {
            uint2 u = __ldg(&vs[i]);
            __half2 lo = *(__half2*)&u.x;
            __half2 hi = *(__half2*)&u.y;
            Vt[(4*i + 0) * VSTR + tid] = __low2half(lo);
            Vt[(4*i + 1) * VSTR + tid] = __high2half(lo);
            Vt[(4*i + 2) * VSTR + tid] = __low2half(hi);
            Vt[(4*i + 3) * VSTR + tid] = __high2half(hi);
        }
    }

    // ---- Q fragments: direct uint32 reads of packed half2 pairs ----
    int q0 = warp * 32;
    uint32_t aq[2][4][4];
    #pragma unroll
    for (int mf = 0; mf < 2; mf++) {
        const __half* qr0 = base + (size_t)(q0 + mf * 16 + quad) * QKVN;
        const __half* qr1 = qr0 + (size_t)8 * QKVN;
        #pragma unroll
        for (int kk = 0; kk < 4; kk++) {
            int kb = kk * 16;
            aq[mf][kk][0] = __ldg((const uint32_t*)(qr0 + kb + 2*r));
            aq[mf][kk][1] = __ldg((const uint32_t*)(qr1 + kb + 2*r));
            aq[mf][kk][2] = __ldg((const uint32_t*)(qr0 + kb + 2*r + 8));
            aq[mf][kk][3] = __ldg((const uint32_t*)(qr1 + kb + 2*r + 8));
        }
    }
    __syncthreads();

    float oacc[2][8][4];
    #pragma unroll
    for (int mf = 0; mf < 2; mf++)
        #pragma unroll
        for (int n = 0; n < 8; n++)
            #pragma unroll
            for (int q = 0; q < 4; q++) oacc[mf][n][q] = 0.f;
    float rsum[2][2] = {{0.f, 0.f}, {0.f, 0.f}};

    for (int s0 = 0; s0 < TSEQ; s0 += 64) {
        #pragma unroll
        for (int mf = 0; mf < 2; mf++) {
            // ---- S = Q K^T for all 8 key n-tiles of this chunk ----
            float sacc[8][4];
            #pragma unroll
            for (int j = 0; j < 8; j++)
                #pragma unroll
                for (int q = 0; q < 4; q++) sacc[j][q] = 0.f;

            #pragma unroll
            for (int kk = 0; kk < 4; kk++) {
                #pragma unroll
                for (int j = 0; j < 8; j++) {
                    const __half* kp = Kh + (size_t)(s0 + j * 8 + quad) * KSTR
                                       + kk * 16 + 2 * r;
                    uint32_t bf[2] = { *(const uint32_t*)kp, *(const uint32_t*)(kp + 8) };
                    mma_f16(sacc[j], aq[mf][kk], bf);
                }
            }

            // ---- exp + pack directly into PV A-fragments (C-frag == A-frag map) ----
            uint32_t ap[4][4];
            #pragma unroll
            for (int j = 0; j < 8; j++) {
                float w0 = __expf(sacc[j][0]);
                float w1 = __expf(sacc[j][1]);
                float w2 = __expf(sacc[j][2]);
                float w3 = __expf(sacc[j][3]);
                rsum[mf][0] += w0 + w1;
                rsum[mf][1] += w2 + w3;
                int kk = j >> 1, hi = (j & 1) * 2;
                ap[kk][hi]     = h2u(w0, w1);
                ap[kk][hi + 1] = h2u(w2, w3);
            }

            // ---- O += P V  (B = Vt [n=d][k=seq]) ----
            #pragma unroll
            for (int kk = 0; kk < 4; kk++) {
                #pragma unroll
                for (int n = 0; n < 8; n++) {
                    const __half* vp = Vt + (size_t)(n * 8 + quad) * VSTR + s0 + kk * 16 + 2 * r;
                    uint32_t bf[2] = { *(const uint32_t*)vp, *(const uint32_t*)(vp + 8) };
                    mma_f16(oacc[mf][n], ap[kk], bf);
                }
            }
        }
    }

    // ---- normalize + write (fp16) ----
    #pragma unroll
    for (int mf = 0; mf < 2; mf++) {
        float v0 = rsum[mf][0], v1 = rsum[mf][1];
        v0 += __shfl_xor_sync(0xffffffffu, v0, 1);
        v0 += __shfl_xor_sync(0xffffffffu, v0, 2);
        v1 += __shfl_xor_sync(0xffffffffu, v1, 1);
        v1 += __shfl_xor_sync(0xffffffffu, v1, 2);
        float inv0 = 1.0f / v0, inv1 = 1.0f / v1;
        int row0 = q0 + mf * 16 + quad;
        __half* o0 = att + ((size_t)b * TSEQ + row0) * CDIM + h * HSZ;
        __half* o1 = o0 + (size_t)8 * CDIM;
        #pragma unroll
        for (int n = 0; n < 8; n++) {
            int col = n * 8 + 2 * r;
            *(__half2*)&o0[col] = __floats2half2_rn(oacc[mf][n][0] * inv0,
                                                    oacc[mf][n][1] * inv0);
            *(__half2*)&o1[col] = __floats2half2_rn(oacc[mf][n][2] * inv1,
                                                    oacc[mf][n][3] * inv1);
        }
    }
}

// ---------------- launch ----------------
extern "C" void kernel_launch(void* const* d_in, const int* in_sizes, int n_in,
                              void* d_out, int out_size) {
    const float* x   = (const float*)d_in[0];
    const float* Wq  = (const float*)d_in[1];
    const float* bq  = (const float*)d_in[2];
    const float* Wk  = (const float*)d_in[3];
    const float* bk  = (const float*)d_in[4];
    const float* Wv  = (const float*)d_in[5];
    const float* bv  = (const float*)d_in[6];
    const float* Wo  = (const float*)d_in[7];
    const float* bo  = (const float*)d_in[8];
    const float* W1  = (const float*)d_in[9];
    const float* b1  = (const float*)d_in[10];
    const float* W2  = (const float*)d_in[11];
    const float* b2  = (const float*)d_in[12];
    const float* g1  = (const float*)d_in[13];
    const float* be1 = (const float*)d_in[14];
    const float* g2  = (const float*)d_in[15];
    const float* be2 = (const float*)d_in[16];
    float* out = (float*)d_out;

    __half *p_h, *p_qkv, *p_att, *p_h2, *p_hidden, *p_Wqkv, *p_Wo, *p_W1, *p_W2;
    float *p_x2, *p_bqkv;
    cudaGetSymbolAddress((void**)&p_h,      g_h);
    cudaGetSymbolAddress((void**)&p_qkv,    g_qkv);
    cudaGetSymbolAddress((void**)&p_att,    g_att);
    cudaGetSymbolAddress((void**)&p_x2,     g_x2);
    cudaGetSymbolAddress((void**)&p_h2,     g_h2);
    cudaGetSymbolAddress((void**)&p_hidden, g_hidden);
    cudaGetSymbolAddress((void**)&p_Wqkv,   g_Wqkv);
    cudaGetSymbolAddress((void**)&p_bqkv,   g_bqkv);
    cudaGetSymbolAddress((void**)&p_Wo,     g_Wo);
    cudaGetSymbolAddress((void**)&p_W1,     g_W1);
    cudaGetSymbolAddress((void**)&p_W2,     g_W2);

    // Idempotent, non-stream, deterministic: safe on every call (no static guards).
    cudaFuncSetAttribute(attn_tc_kernel, cudaFuncAttributeMaxDynamicSharedMemorySize,
                         ATTN_SMEM);
    cudaFuncSetAttribute(hgemm, cudaFuncAttributeMaxDynamicSharedMemorySize,
                         HG_SMEM);

    // 0. weight prep (transpose + fp16)
    {
        int total = CDIM*CDIM + C4DIM*CDIM + CDIM*C4DIM;
        wprep_kernel<<<(total + 255) / 256, 256>>>(Wo, W1, W2);
    }
    {
        int total = QKVN * CDIM;
        repack_kernel<<<(total + 255) / 256, 256>>>(Wq, Wk, Wv, bq, bk, bv);
    }
    // 2. ln1 -> fp16 (warp-per-row)
    ln_kernel<<<MTOK / 8, 256>>>(x, g1, be1, p_h);
    // 3. fused QKV projection (fp16 TC) -> fp16 qkv, Q pre-scaled by 1/8
    hgemm<<<dim3(QKVN / 128, MTOK / 128), 256, HG_SMEM>>>(
        p_h, p_Wqkv, p_bqkv, nullptr, p_qkv, MTOK, QKVN, CDIM, 0, 1, 1);
    // 4. attention (fp16 TC flash, register P) -> fp16 att
    attn_tc_kernel<<<BATCH * NHEAD, 256, ATTN_SMEM>>>(p_qkv, p_att);
    // 5. out projection + residual (fp16 TC) -> fp32 x2
    hgemm<<<dim3(CDIM / 128, MTOK / 128), 256, HG_SMEM>>>(
        p_att, p_Wo, bo, x, p_x2, MTOK, CDIM, CDIM, 0, 0, 0);
    // 6. ln2 -> fp16 (warp-per-row)
    ln_kernel<<<MTOK / 8, 256>>>(p_x2, g2, be2, p_h2);
    // 7. FFN up + GELU (fp16 TC) -> fp16 hidden
    hgemm<<<dim3(C4DIM / 128, MTOK / 128), 256, HG_SMEM>>>(
        p_h2, p_W1, b1, nullptr, p_hidden, MTOK, C4DIM, CDIM, 1, 1, 0);
    // 8. FFN down + bias + residual -> fp32 out
    hgemm<<<dim3(CDIM / 128, MTOK / 128), 256, HG_SMEM>>>(
        p_hidden, p_W2, b2, p_x2, out, MTOK, CDIM, C4DIM, 0, 0, 0);
}